// round 12
// baseline (speedup 1.0000x reference)
#include <cuda_runtime.h>
#include <math.h>

#define NIMG 16
#define NCLS 80
#define NREF 256
#define CAP  8192
#define LCAP 8192
#define THWPAD 20480
#define NSEG 6480       // segments per image (class-aligned 256-chunks)
#define NSEGPAD 6528

#define MAGICF 12582912.0f              // 1.5 * 2^23 : round-to-nearest-int magic
#define KC (127 - 0x4B400000)           // exponent rebias for magic-rounded y
#define C1F 0.70710678f                 // quad minimax of 2^f on [-0.5, 0.5]
#define C2F 0.24264069f

typedef unsigned long long u64;

// ---------------- scratch (device globals; no allocs) ----------------
__device__ float g_ctrD[NIMG * THWPAD];             // (1 + e^{-ctr}), padded layout
__device__ float g_segD[NIMG * NSEGPAD];            // per-segment min D
__device__ int   g_bcut[NIMG];
__device__ int   g_cnt[NIMG];
__device__ int   g_lcnt[NIMG];
__device__ int   g_seglist[NIMG][LCAP];
__device__ unsigned long long g_cand[NIMG][CAP];

struct P5 { const float* lg[5]; const float* rg[5]; const float* ct[5]; const float* lc[5]; };

__constant__ int c_HW[5]   = {15200, 3800, 950, 247, 70};
__constant__ int c_hwb2[5] = {0, 15232, 19072, 20032, 20288};  // 16B-aligned bases
__constant__ int c_rb[5]   = {0, 1216000, 1520000, 1596000, 1615760};
__constant__ float c_str[5] = {8.f, 16.f, 32.f, 64.f, 128.f};

// ---- packed f32x2 helpers (Blackwell PTX) ----
__device__ __forceinline__ u64 pk2(float lo, float hi) {
    u64 r; asm("mov.b64 %0,{%1,%2};" : "=l"(r) : "f"(lo), "f"(hi)); return r;
}
__device__ __forceinline__ void upk2(u64 v, float& lo, float& hi) {
    asm("mov.b64 {%0,%1},%2;" : "=f"(lo), "=f"(hi) : "l"(v));
}
__device__ __forceinline__ u64 mul2(u64 a, u64 b) {
    u64 r; asm("mul.rn.f32x2 %0,%1,%2;" : "=l"(r) : "l"(a), "l"(b)); return r;
}
__device__ __forceinline__ u64 add2(u64 a, u64 b) {
    u64 r; asm("add.rn.f32x2 %0,%1,%2;" : "=l"(r) : "l"(a), "l"(b)); return r;
}
__device__ __forceinline__ u64 fma2(u64 a, u64 b, u64 c) {
    u64 r; asm("fma.rn.f32x2 %0,%1,%2,%3;" : "=l"(r) : "l"(a), "l"(b), "l"(c)); return r;
}

// Scalar surrogate e^{-x}: magic-round exp2 split + quad minimax. Contraction-proof
// (__fmul_rn/__fadd_rn/fmaf) so it is BITWISE identical to the packed f32x2 path.
// MUST stay in sync with the packed sequence in k_minred.
__device__ __forceinline__ float expneg_s(float x) {
    float u = __fmul_rn(-1.44269504f, x);
    float y = __fadd_rn(u, MAGICF);
    int iy = __float_as_int(y);
    float yf = __fadd_rn(y, -MAGICF);
    float f = fmaf(yf, -1.0f, u);
    float pm = fmaf(fmaf(C2F, f, C1F), f, 1.0f);
    float sc = __int_as_float((iy + KC) << 23);
    return __fmul_rn(pm, sc);
}

// surrogate inverse-score key, NO gate (gated elems have D>20 >> cut ~2-4)
__device__ __forceinline__ float Dkey_s(float a, float cd) {
    return fmaf(expneg_s(a), cd, cd);             // (1 + e^-a) * cd
}

// Reference-exact sigmoid (libdevice expf == XLA f32 exp), survivors only.
__device__ __forceinline__ float sig_ref(float x) {
    return 1.0f / (1.0f + expf(-x));
}

struct Seg { int l, c, hw0, HW; };
__device__ __forceinline__ Seg seg_decode(int wid) {
    Seg s;
    if (wid < 4800)      { s.l=0; s.c=wid/60;  s.hw0=(wid-s.c*60)<<8;  s.HW=15200; }
    else if (wid < 6000) { int t=wid-4800; s.l=1; s.c=t/15; s.hw0=(t-s.c*15)<<8; s.HW=3800; }
    else if (wid < 6320) { int t=wid-6000; s.l=2; s.c=t>>2; s.hw0=(t&3)<<8; s.HW=950; }
    else if (wid < 6400) { s.l=3; s.c=wid-6320; s.hw0=0; s.HW=247; }
    else                 { s.l=4; s.c=wid-6400; s.hw0=0; s.HW=70; }
    return s;
}

// vectorized: one thread per 4 consecutive padded slots; float4 fast path for
// the aligned level-0/1 interiors, scalar (bitwise-identical expneg_s) elsewhere
__global__ void k_ctr(P5 p) {
    int q = blockIdx.x * blockDim.x + threadIdx.x;
    if (q < NIMG) { g_cnt[q] = 0; g_lcnt[q] = 0; }
    if (q >= NIMG * (THWPAD / 4)) return;
    int n = q / (THWPAD / 4);
    int g = (q - n * (THWPAD / 4)) * 4;
    if (g + 4 <= 15200) {                               // level 0 interior
        float4 v = *(const float4*)(p.ct[0] + n * 15200 + g);
        float4 o;
        o.x = __fadd_rn(1.0f, expneg_s(v.x)); o.y = __fadd_rn(1.0f, expneg_s(v.y));
        o.z = __fadd_rn(1.0f, expneg_s(v.z)); o.w = __fadd_rn(1.0f, expneg_s(v.w));
        *(float4*)(g_ctrD + n * THWPAD + g) = o;
    } else if (g >= 15232 && g + 4 <= 19032) {          // level 1 interior
        float4 v = *(const float4*)(p.ct[1] + n * 3800 + (g - 15232));
        float4 o;
        o.x = __fadd_rn(1.0f, expneg_s(v.x)); o.y = __fadd_rn(1.0f, expneg_s(v.y));
        o.z = __fadd_rn(1.0f, expneg_s(v.z)); o.w = __fadd_rn(1.0f, expneg_s(v.w));
        *(float4*)(g_ctrD + n * THWPAD + g) = o;
    } else {
        #pragma unroll
        for (int k = 0; k < 4; k++) {
            int gg = g + k;
            int l = -1, hw = 0;
            if (gg < 15200)                    { l = 0; hw = gg; }
            else if (gg >= 15232 && gg < 19032){ l = 1; hw = gg - 15232; }
            else if (gg >= 19072 && gg < 20022){ l = 2; hw = gg - 19072; }
            else if (gg >= 20032 && gg < 20279){ l = 3; hw = gg - 20032; }
            else if (gg >= 20288 && gg < 20358){ l = 4; hw = gg - 20288; }
            if (l >= 0)
                g_ctrD[n * THWPAD + gg] =
                    __fadd_rn(1.0f, expneg_s(p.ct[l][n * c_HW[l] + hw]));
        }
    }
}

// full pass: per-segment (256-elem) min of surrogate D. Packed f32x2 math for
// levels 0/1 (16B-aligned rows, 94% of data); scalar for levels 2-4 + tails.
__global__ void k_minred(P5 p) {
    int n = blockIdx.y;
    int wid = blockIdx.x * 8 + (threadIdx.x >> 5);
    int lane = threadIdx.x & 31;
    if (wid >= NSEG) return;
    Seg sg = seg_decode(wid);
    const float* lg = p.lg[sg.l] + ((size_t)n * NCLS + sg.c) * sg.HW;
    const float* cd = g_ctrD + n * THWPAD + c_hwb2[sg.l];
    int base = sg.hw0 + lane * 8;
    float m = 3.4e38f;
    if (sg.l < 2 && base + 8 <= sg.HW) {
        float4 a0 = *(const float4*)(lg + base);
        float4 a1 = *(const float4*)(lg + base + 4);
        float4 d0 = *(const float4*)(cd + base);
        float4 d1 = *(const float4*)(cd + base + 4);
        u64 A[4] = {pk2(a0.x,a0.y), pk2(a0.z,a0.w), pk2(a1.x,a1.y), pk2(a1.z,a1.w)};
        u64 C[4] = {pk2(d0.x,d0.y), pk2(d0.z,d0.w), pk2(d1.x,d1.y), pk2(d1.z,d1.w)};
        const u64 NL2  = pk2(-1.44269504f, -1.44269504f);
        const u64 MG   = pk2(MAGICF, MAGICF);
        const u64 NMG  = pk2(-MAGICF, -MAGICF);
        const u64 NONE2= pk2(-1.0f, -1.0f);
        const u64 C2P  = pk2(C2F, C2F);
        const u64 C1P  = pk2(C1F, C1F);
        const u64 ONE2 = pk2(1.0f, 1.0f);
        #pragma unroll
        for (int i = 0; i < 4; i++) {
            u64 u  = mul2(A[i], NL2);
            u64 y  = add2(u, MG);
            float ylo, yhi; upk2(y, ylo, yhi);
            u64 yf = add2(y, NMG);
            u64 f  = fma2(yf, NONE2, u);
            u64 pm = fma2(fma2(C2P, f, C1P), f, ONE2);
            float slo = __int_as_float((__float_as_int(ylo) + KC) << 23);
            float shi = __int_as_float((__float_as_int(yhi) + KC) << 23);
            u64 e  = mul2(pm, pk2(slo, shi));
            u64 D  = fma2(e, C[i], C[i]);
            float dlo, dhi; upk2(D, dlo, dhi);
            m = fminf(m, fminf(dlo, dhi));
        }
    } else {
        #pragma unroll
        for (int k = 0; k < 8; k++) {
            int h = base + k;
            if (h < sg.HW) m = fminf(m, Dkey_s(lg[h], cd[h]));
        }
    }
    #pragma unroll
    for (int o = 16; o; o >>= 1) m = fminf(m, __shfl_xor_sync(0xffffffffu, m, o));
    if (lane == 0) g_segD[n * NSEGPAD + wid] = m;
}

// ascending rank-select over 4096 buckets of seg-mins, then build seglist
__global__ void __launch_bounds__(512) k_cut() {
    __shared__ int hist[4096];
    __shared__ int wtot[16], wpre[16];
    __shared__ int bres;
    int n = blockIdx.x, tid = threadIdx.x, nt = blockDim.x;
    int lane = tid & 31, w = tid >> 5;
    for (int i = tid; i < 4096; i += nt) hist[i] = 0;
    if (tid == 0) bres = 4095;
    __syncthreads();
    for (int i = tid; i < NSEG; i += nt) {
        unsigned b = __float_as_uint(g_segD[n * NSEGPAD + i]) >> 19;
        atomicAdd(&hist[min(b, 4095u)], 1);
    }
    __syncthreads();
    int s8 = 0;
    #pragma unroll
    for (int j = 0; j < 8; j++) s8 += hist[tid * 8 + j];
    int pre = s8;
    #pragma unroll
    for (int o = 1; o < 32; o <<= 1) {
        int t2 = __shfl_up_sync(0xffffffffu, pre, o);
        if (lane >= o) pre += t2;
    }
    if (lane == 31) wtot[w] = pre;
    __syncthreads();
    if (tid < 16) {
        int v = wtot[tid];
        int s = v;
        #pragma unroll
        for (int o = 1; o < 16; o <<= 1) {
            int t2 = __shfl_up_sync(0xffffu, s, o);
            if (tid >= o) s += t2;
        }
        wpre[tid] = s - v;
    }
    __syncthreads();
    int excl = wpre[w] + (pre - s8);
    if (excl < NREF && excl + s8 >= NREF) {
        int cum = excl;
        #pragma unroll
        for (int b = 0; b < 8; b++) {
            cum += hist[tid * 8 + b];
            if (cum >= NREF) { bres = tid * 8 + b; break; }
        }
    }
    __syncthreads();
    int bc = min(bres + 1, 4095);       // +1 bucket: surrogate-vs-exact slop
    if (tid == 0) g_bcut[n] = bc;
    for (int i = tid; i < NSEG; i += nt) {
        unsigned b = __float_as_uint(g_segD[n * NSEGPAD + i]) >> 19;
        if ((int)b <= bc) {
            int pos = atomicAdd(&g_lcnt[n], 1);
            if (pos < LCAP) g_seglist[n][pos] = i;
        }
    }
}

// flattened quad loop, uniform round count (full warp masks), warp-aggregated
// candidate emission: one global atomic per warp-survivor-group.
__global__ void k_compact(P5 p) {
    int n = blockIdx.y;
    int bcut = g_bcut[n];
    int lcnt = min(g_lcnt[n], LCAP);
    int total = lcnt << 6;              // 64 quads per 256-elem segment
    int stride = gridDim.x * blockDim.x;
    int base = blockIdx.x * blockDim.x + threadIdx.x;
    int rounds = (total + stride - 1) / stride;
    int lanelt = __popc(__activemask() & ((1u << (threadIdx.x & 31)) - 1)); (void)lanelt;
    unsigned ltmask = (1u << (threadIdx.x & 31)) - 1;
    for (int r = 0; r < rounds; r++) {
        int e = base + r * stride;
        bool act = e < total;
        float aa[4], dd[4], cv[4];
        int rnk[4];
        bool flag[4] = {false, false, false, false};
        if (act) {
            int si = g_seglist[n][e >> 6];
            Seg sg = seg_decode(si);
            int hw = sg.hw0 + ((e & 63) << 2);
            const float* lg = p.lg[sg.l] + ((size_t)n * NCLS + sg.c) * sg.HW;
            const float* cd = g_ctrD + n * THWPAD + c_hwb2[sg.l];
            const float* ctp = p.ct[sg.l] + (size_t)n * sg.HW;
            int rb = c_rb[sg.l];
            if (sg.l < 2 && hw + 4 <= sg.HW) {
                float4 a = *(const float4*)(lg + hw);
                float4 d = *(const float4*)(cd + hw);
                aa[0]=a.x; aa[1]=a.y; aa[2]=a.z; aa[3]=a.w;
                dd[0]=d.x; dd[1]=d.y; dd[2]=d.z; dd[3]=d.w;
                #pragma unroll
                for (int k = 0; k < 4; k++) {
                    if ((int)(__float_as_uint(Dkey_s(aa[k], dd[k])) >> 19) <= bcut) {
                        cv[k] = ctp[hw + k];
                        rnk[k] = rb + (hw + k) * NCLS + sg.c;
                        flag[k] = true;
                    }
                }
            } else {
                #pragma unroll
                for (int k = 0; k < 4; k++) {
                    int h = hw + k;
                    if (h < sg.HW) {
                        float a = lg[h];
                        float d = cd[h];
                        if ((int)(__float_as_uint(Dkey_s(a, d)) >> 19) <= bcut) {
                            aa[k] = a; cv[k] = ctp[h];
                            rnk[k] = rb + h * NCLS + sg.c;
                            flag[k] = true;
                        }
                    }
                }
            }
        }
        #pragma unroll
        for (int k = 0; k < 4; k++) {
            bool emit = false;
            unsigned vb = 0;
            if (flag[k]) {
                float sa = sig_ref(aa[k]);
                if (sa > 0.05f) {                       // exact reference gate
                    float v = sa * sig_ref(cv[k]);
                    if (v > 0.0f) { emit = true; vb = __float_as_uint(v); }
                }
            }
            unsigned bal = __ballot_sync(0xffffffffu, emit);
            if (bal) {
                int cnt2 = __popc(bal);
                int ldr = __ffs(bal) - 1;
                int pos0 = 0;
                if ((threadIdx.x & 31) == ldr)
                    pos0 = atomicAdd(&g_cnt[n], cnt2);
                pos0 = __shfl_sync(0xffffffffu, pos0, ldr);
                if (emit) {
                    int pos = pos0 + __popc(bal & ltmask);
                    if (pos < CAP)
                        g_cand[n][pos] = ((u64)vb << 32) |
                                         (0x7FFFFFFFu - (unsigned)rnk[k]);
                }
            }
        }
    }
}

__global__ void __launch_bounds__(1024) k_sort(P5 p, float* out) {
    __shared__ union { int hist[8192]; unsigned long long buf[2048]; } u;  // 32KB
    __shared__ int wtot[32], wsuf[32];
    __shared__ int m, bs;
    int n = blockIdx.x, tid = threadIdx.x, nt = blockDim.x;
    int lane = tid & 31, w = tid >> 5;
    int cnt = min(g_cnt[n], CAP);
    for (int i = tid; i < 8192; i += nt) u.hist[i] = 0;
    if (tid == 0) { m = 0; bs = 0; }
    __syncthreads();

    for (int i = tid; i < cnt; i += nt)
        atomicAdd(&u.hist[(int)(g_cand[n][i] >> 51)], 1);
    __syncthreads();

    // hierarchical descending rank-select over 8192 buckets
    int s8 = 0;
    #pragma unroll
    for (int j = 0; j < 8; j++) s8 += u.hist[tid * 8 + j];
    int suf = s8;
    #pragma unroll
    for (int o = 1; o < 32; o <<= 1) {
        int t2 = __shfl_down_sync(0xffffffffu, suf, o);
        if (lane + o < 32) suf += t2;
    }
    if (lane == 0) wtot[w] = suf;
    __syncthreads();
    if (tid < 32) {
        int v = wtot[tid];
        int s = v;
        #pragma unroll
        for (int o = 1; o < 32; o <<= 1) {
            int t2 = __shfl_down_sync(0xffffffffu, s, o);
            if (tid + o < 32) s += t2;
        }
        wsuf[tid] = s - v;
    }
    __syncthreads();
    int above = wsuf[w] + (suf - s8);
    if (above < NREF && above + s8 >= NREF) {
        int cum = above;
        #pragma unroll
        for (int b = 7; b >= 0; b--) {
            cum += u.hist[tid * 8 + b];
            if (cum >= NREF) { bs = tid * 8 + b; break; }
        }
    }
    __syncthreads();
    int bcut2 = bs;
    __syncthreads();                     // hist dead; buf overlay safe

    for (int i = tid; i < cnt; i += nt) {
        unsigned long long kk = g_cand[n][i];
        if ((int)(kk >> 51) >= bcut2) {
            int pos = atomicAdd(&m, 1);
            if (pos < 2048) u.buf[pos] = kk;
        }
    }
    __syncthreads();
    int mm = min(m, 2048);
    int S = (mm <= 512) ? 512 : 2048;    // adaptive sort width (m is ~256+eps)
    for (int i = tid; i < S; i += nt) if (i >= mm) u.buf[i] = 0ULL;
    __syncthreads();

    // bitonic sort descending; keys unique (rank embedded) -> deterministic
    for (int k = 2; k <= S; k <<= 1) {
        for (int j = k >> 1; j > 0; j >>= 1) {
            for (int i = tid; i < S; i += nt) {
                int ixj = i ^ j;
                if (ixj > i) {
                    unsigned long long x = u.buf[i], y = u.buf[ixj];
                    bool desc = ((i & k) == 0);
                    if (desc ? (x < y) : (x > y)) { u.buf[i] = y; u.buf[ixj] = x; }
                }
            }
            __syncthreads();
        }
    }

    if (tid < NREF) {
        unsigned long long kk = u.buf[tid];
        float sc = 0.f, x0 = 0.f, y0 = 0.f, x1 = 0.f, y1 = 0.f;
        int cls = 0, lvl = 0;
        if (kk) {
            float v = __uint_as_float((unsigned)(kk >> 32));
            unsigned rank = 0x7FFFFFFFu - (unsigned)(kk & 0xFFFFFFFFu);
            int l;
            if (rank < 1216000u) l = 0;
            else if (rank < 1520000u) l = 1;
            else if (rank < 1596000u) l = 2;
            else if (rank < 1615760u) l = 3;
            else l = 4;
            int HWl = c_HW[l];
            int r = (int)rank - c_rb[l];
            int loc = r / NCLS;
            cls = r - NCLS * loc;
            lvl = l;
            float strf = c_str[l];
            float px = p.lc[l][2 * loc], py = p.lc[l][2 * loc + 1];
            const float* rg = p.rg[l] + (size_t)n * 4 * HWl;
            float r0 = rg[loc] * strf;
            float r1 = rg[HWl + loc] * strf;
            float r2 = rg[2 * HWl + loc] * strf;
            float r3 = rg[3 * HWl + loc] * strf;
            sc = sqrtf(v);
            x0 = px - r0; y0 = py - r1; x1 = px + r2; y1 = py + r3;
        }
        int o = n * NREF + tid;
        out[o] = sc;
        float* ob = out + NIMG * NREF;
        ob[o * 4 + 0] = x0; ob[o * 4 + 1] = y0;
        ob[o * 4 + 2] = x1; ob[o * 4 + 3] = y1;
        float* oc = out + NIMG * NREF * 5;
        oc[o] = (float)cls;
        float* ol = out + NIMG * NREF * 6;
        ol[o] = (float)lvl;
    }
}

extern "C" void kernel_launch(void* const* d_in, const int* in_sizes, int n_in,
                              void* d_out, int out_size) {
    P5 p;
    for (int l = 0; l < 5; l++) {
        p.lg[l] = (const float*)d_in[4 * l + 0];
        p.rg[l] = (const float*)d_in[4 * l + 1];
        p.ct[l] = (const float*)d_in[4 * l + 2];
        p.lc[l] = (const float*)d_in[4 * l + 3];
    }
    k_ctr<<<(NIMG * (THWPAD / 4) + 255) / 256, 256>>>(p);
    dim3 g(810, NIMG);       // 810*8 warps >= 6480 segments
    k_minred<<<g, 256>>>(p);
    k_cut<<<NIMG, 512>>>();
    dim3 gc(64, NIMG);       // 16K threads/image, ~1.3 quads per thread
    k_compact<<<gc, 256>>>(p);
    k_sort<<<NIMG, 1024>>>(p, (float*)d_out);
}

// round 13
// speedup vs baseline: 1.1458x; 1.1458x over previous
#include <cuda_runtime.h>
#include <math.h>

#define NIMG 16
#define NCLS 80
#define NREF 256
#define CAP  8192
#define LCAP 8192
#define NSEG 6480       // segments per image (class-aligned 256-chunks)
#define NSEGPAD 6528
#define NW2  810        // minred warps per image (8 classes x 256 hw each)

#define MAGICF 12582912.0f              // 1.5 * 2^23 : round-to-nearest-int magic
#define KC (127 - 0x4B400000)           // exponent rebias for magic-rounded y
#define C1F 0.70710678f                 // quad minimax of 2^f on [-0.5, 0.5]
#define C2F 0.24264069f

typedef unsigned long long u64;

// ---------------- scratch (device globals; no allocs) ----------------
__device__ float g_segD[NIMG * NSEGPAD];            // per-segment min D
__device__ int   g_bcut[NIMG];
__device__ int   g_cnt[NIMG];
__device__ int   g_lcnt[NIMG];
__device__ int   g_seglist[NIMG][LCAP];
__device__ unsigned long long g_cand[NIMG][CAP];

struct P5 { const float* lg[5]; const float* rg[5]; const float* ct[5]; const float* lc[5]; };

__constant__ int c_HW[5]   = {15200, 3800, 950, 247, 70};
__constant__ int c_rb[5]   = {0, 1216000, 1520000, 1596000, 1615760};
__constant__ int c_spc[5]  = {60, 15, 4, 1, 1};
__constant__ int c_segb[5] = {0, 4800, 6000, 6320, 6400};
__constant__ float c_str[5] = {8.f, 16.f, 32.f, 64.f, 128.f};

// ---- packed f32x2 helpers (Blackwell PTX) ----
__device__ __forceinline__ u64 pk2(float lo, float hi) {
    u64 r; asm("mov.b64 %0,{%1,%2};" : "=l"(r) : "f"(lo), "f"(hi)); return r;
}
__device__ __forceinline__ void upk2(u64 v, float& lo, float& hi) {
    asm("mov.b64 {%0,%1},%2;" : "=f"(lo), "=f"(hi) : "l"(v));
}
__device__ __forceinline__ u64 mul2(u64 a, u64 b) {
    u64 r; asm("mul.rn.f32x2 %0,%1,%2;" : "=l"(r) : "l"(a), "l"(b)); return r;
}
__device__ __forceinline__ u64 add2(u64 a, u64 b) {
    u64 r; asm("add.rn.f32x2 %0,%1,%2;" : "=l"(r) : "l"(a), "l"(b)); return r;
}
__device__ __forceinline__ u64 fma2(u64 a, u64 b, u64 c) {
    u64 r; asm("fma.rn.f32x2 %0,%1,%2,%3;" : "=l"(r) : "l"(a), "l"(b), "l"(c)); return r;
}

// Scalar surrogate e^{-x}: magic-round exp2 split + quad minimax. Contraction-proof
// (__fmul_rn/__fadd_rn/fmaf): BITWISE identical to the packed expneg2 below.
__device__ __forceinline__ float expneg_s(float x) {
    float u = __fmul_rn(-1.44269504f, x);
    float y = __fadd_rn(u, MAGICF);
    int iy = __float_as_int(y);
    float yf = __fadd_rn(y, -MAGICF);
    float f = fmaf(yf, -1.0f, u);
    float pm = fmaf(fmaf(C2F, f, C1F), f, 1.0f);
    float sc = __int_as_float((iy + KC) << 23);
    return __fmul_rn(pm, sc);
}

// packed twin of expneg_s (per-lane IEEE rn ops -> identical bits)
__device__ __forceinline__ u64 expneg2(u64 x) {
    const u64 NL2  = pk2(-1.44269504f, -1.44269504f);
    const u64 MG   = pk2(MAGICF, MAGICF);
    const u64 NMG  = pk2(-MAGICF, -MAGICF);
    const u64 NONE = pk2(-1.0f, -1.0f);
    const u64 C2P  = pk2(C2F, C2F);
    const u64 C1P  = pk2(C1F, C1F);
    const u64 ONE  = pk2(1.0f, 1.0f);
    u64 u = mul2(x, NL2);
    u64 y = add2(u, MG);
    float ylo, yhi; upk2(y, ylo, yhi);
    u64 yf = add2(y, NMG);
    u64 f  = fma2(yf, NONE, u);
    u64 pm = fma2(fma2(C2P, f, C1P), f, ONE);
    float slo = __int_as_float((__float_as_int(ylo) + KC) << 23);
    float shi = __int_as_float((__float_as_int(yhi) + KC) << 23);
    return mul2(pm, pk2(slo, shi));
}

// surrogate inverse-score key from logit + precomputed denom cd = 1+e^-c
__device__ __forceinline__ float Dkey_s(float a, float cd) {
    return fmaf(expneg_s(a), cd, cd);             // (1 + e^-a) * cd
}

// Reference-exact sigmoid (libdevice expf == XLA f32 exp), survivors only.
__device__ __forceinline__ float sig_ref(float x) {
    return 1.0f / (1.0f + expf(-x));
}

struct Seg { int l, c, hw0, HW; };
__device__ __forceinline__ Seg seg_decode(int wid) {
    Seg s;
    if (wid < 4800)      { s.l=0; s.c=wid/60;  s.hw0=(wid-s.c*60)<<8;  s.HW=15200; }
    else if (wid < 6000) { int t=wid-4800; s.l=1; s.c=t/15; s.hw0=(t-s.c*15)<<8; s.HW=3800; }
    else if (wid < 6320) { int t=wid-6000; s.l=2; s.c=t>>2; s.hw0=(t&3)<<8; s.HW=950; }
    else if (wid < 6400) { s.l=3; s.c=wid-6320; s.hw0=0; s.HW=247; }
    else                 { s.l=4; s.c=wid-6400; s.hw0=0; s.HW=70; }
    return s;
}

// full pass: each warp handles 8 classes x 256 hw. ct loaded ONCE per window,
// surrogate denom computed inline (k_ctr kernel deleted). Packed f32x2 for
// levels 0/1; scalar (bitwise-identical) for levels 2-4.
__global__ void k_minred(P5 p) {
    int n = blockIdx.y;
    int w2 = blockIdx.x * 8 + (threadIdx.x >> 5);
    int lane = threadIdx.x & 31;
    if (w2 >= NW2) return;
    int l, grp, chunk;
    if (w2 < 600)      { l = 0; grp = w2 / 60;  chunk = w2 - grp * 60; }
    else if (w2 < 750) { int t = w2 - 600; l = 1; grp = t / 15; chunk = t - grp * 15; }
    else if (w2 < 790) { int t = w2 - 750; l = 2; grp = t >> 2; chunk = t & 3; }
    else if (w2 < 800) { l = 3; grp = w2 - 790; chunk = 0; }
    else               { l = 4; grp = w2 - 800; chunk = 0; }
    int HW = c_HW[l];
    int base = (chunk << 8) + lane * 8;
    const float* ctp = p.ct[l] + (size_t)n * HW;
    const float* lg0 = p.lg[l] + ((size_t)n * NCLS + grp * 8) * (size_t)HW;
    float mj[8];
    if (l < 2) {
        bool act = (base + 8 <= HW);     // chunk tails are 8-aligned for l0/l1
        u64 CD0, CD1, CD2, CD3;
        const u64 ONE = pk2(1.0f, 1.0f);
        if (act) {
            float4 t0 = *(const float4*)(ctp + base);
            float4 t1 = *(const float4*)(ctp + base + 4);
            CD0 = add2(expneg2(pk2(t0.x, t0.y)), ONE);
            CD1 = add2(expneg2(pk2(t0.z, t0.w)), ONE);
            CD2 = add2(expneg2(pk2(t1.x, t1.y)), ONE);
            CD3 = add2(expneg2(pk2(t1.z, t1.w)), ONE);
        }
        #pragma unroll
        for (int j = 0; j < 8; j++) {
            float m = 3.4e38f;
            if (act) {
                const float* lg = lg0 + (size_t)j * HW;
                float4 a0 = *(const float4*)(lg + base);
                float4 a1 = *(const float4*)(lg + base + 4);
                u64 D0 = fma2(expneg2(pk2(a0.x, a0.y)), CD0, CD0);
                u64 D1 = fma2(expneg2(pk2(a0.z, a0.w)), CD1, CD1);
                u64 D2 = fma2(expneg2(pk2(a1.x, a1.y)), CD2, CD2);
                u64 D3 = fma2(expneg2(pk2(a1.z, a1.w)), CD3, CD3);
                float x0, x1, x2, x3, x4, x5, x6, x7;
                upk2(D0, x0, x1); upk2(D1, x2, x3);
                upk2(D2, x4, x5); upk2(D3, x6, x7);
                m = fminf(fminf(fminf(x0, x1), fminf(x2, x3)),
                          fminf(fminf(x4, x5), fminf(x6, x7)));
            }
            mj[j] = m;
        }
    } else {
        float cdv[8];
        #pragma unroll
        for (int k = 0; k < 8; k++) {
            int h = base + k;
            cdv[k] = (h < HW) ? __fadd_rn(1.0f, expneg_s(ctp[h])) : 0.0f;
        }
        #pragma unroll
        for (int j = 0; j < 8; j++) {
            const float* lg = lg0 + (size_t)j * HW;
            float m = 3.4e38f;
            #pragma unroll
            for (int k = 0; k < 8; k++) {
                int h = base + k;
                if (h < HW) m = fminf(m, Dkey_s(lg[h], cdv[k]));
            }
            mj[j] = m;
        }
    }
    #pragma unroll
    for (int j = 0; j < 8; j++) {
        float m = mj[j];
        #pragma unroll
        for (int o = 16; o; o >>= 1)
            m = fminf(m, __shfl_xor_sync(0xffffffffu, m, o));
        mj[j] = m;
    }
    if (lane == 0) {
        int sb = c_segb[l], spc = c_spc[l];
        #pragma unroll
        for (int j = 0; j < 8; j++)
            g_segD[n * NSEGPAD + sb + (grp * 8 + j) * spc + chunk] = mj[j];
    }
}

// ascending rank-select over 4096 buckets of seg-mins, then build seglist.
// Also zeroes g_cnt (k_ctr is gone).
__global__ void __launch_bounds__(512) k_cut() {
    __shared__ int hist[4096];
    __shared__ int wtot[16], wpre[16];
    __shared__ int bres, lcnt_s;
    int n = blockIdx.x, tid = threadIdx.x, nt = blockDim.x;
    int lane = tid & 31, w = tid >> 5;
    for (int i = tid; i < 4096; i += nt) hist[i] = 0;
    if (tid == 0) { bres = 4095; lcnt_s = 0; g_cnt[n] = 0; }
    __syncthreads();
    for (int i = tid; i < NSEG; i += nt) {
        unsigned b = __float_as_uint(g_segD[n * NSEGPAD + i]) >> 19;
        atomicAdd(&hist[min(b, 4095u)], 1);
    }
    __syncthreads();
    int s8 = 0;
    #pragma unroll
    for (int j = 0; j < 8; j++) s8 += hist[tid * 8 + j];
    int pre = s8;
    #pragma unroll
    for (int o = 1; o < 32; o <<= 1) {
        int t2 = __shfl_up_sync(0xffffffffu, pre, o);
        if (lane >= o) pre += t2;
    }
    if (lane == 31) wtot[w] = pre;
    __syncthreads();
    if (tid < 16) {
        int v = wtot[tid];
        int s = v;
        #pragma unroll
        for (int o = 1; o < 16; o <<= 1) {
            int t2 = __shfl_up_sync(0xffffu, s, o);
            if (tid >= o) s += t2;
        }
        wpre[tid] = s - v;
    }
    __syncthreads();
    int excl = wpre[w] + (pre - s8);
    if (excl < NREF && excl + s8 >= NREF) {
        int cum = excl;
        #pragma unroll
        for (int b = 0; b < 8; b++) {
            cum += hist[tid * 8 + b];
            if (cum >= NREF) { bres = tid * 8 + b; break; }
        }
    }
    __syncthreads();
    int bc = min(bres + 1, 4095);       // +1 bucket: surrogate-vs-exact slop
    if (tid == 0) g_bcut[n] = bc;
    for (int i = tid; i < NSEG; i += nt) {
        unsigned b = __float_as_uint(g_segD[n * NSEGPAD + i]) >> 19;
        if ((int)b <= bc) {
            int pos = atomicAdd(&lcnt_s, 1);
            if (pos < LCAP) g_seglist[n][pos] = i;
        }
    }
    __syncthreads();
    if (tid == 0) g_lcnt[n] = min(lcnt_s, LCAP);
}

__device__ __forceinline__ void push_cand(int n, float a, float ctr_v, int rnk) {
    float sa = sig_ref(a);
    if (sa > 0.05f) {                           // exact reference gate
        float v = sa * sig_ref(ctr_v);
        if (v > 0.0f) {
            unsigned long long kk =
                ((unsigned long long)__float_as_uint(v) << 32) |
                (0x7FFFFFFFu - (unsigned)rnk);
            int pos = atomicAdd(&g_cnt[n], 1);
            if (pos < CAP) g_cand[n][pos] = kk;
        }
    }
}

// flattened one-quad-per-thread (R10 proven config). Surrogate denom computed
// from the ct value that the exact path needs anyway -> no g_ctrD load.
__global__ void k_compact(P5 p) {
    int n = blockIdx.y;
    int bcut = g_bcut[n];
    int lcnt = g_lcnt[n];
    int total = lcnt << 6;              // 64 quads per 256-elem segment
    int stride = gridDim.x * blockDim.x;
    for (int e = blockIdx.x * blockDim.x + threadIdx.x; e < total; e += stride) {
        int si = g_seglist[n][e >> 6];
        Seg sg = seg_decode(si);
        int hw = sg.hw0 + ((e & 63) << 2);
        const float* lg = p.lg[sg.l] + ((size_t)n * NCLS + sg.c) * sg.HW;
        const float* ctp = p.ct[sg.l] + (size_t)n * sg.HW;
        int rb = c_rb[sg.l];
        if (sg.l < 2 && hw + 4 <= sg.HW) {
            float4 a = *(const float4*)(lg + hw);
            float4 t = *(const float4*)(ctp + hw);
            float aa[4] = {a.x, a.y, a.z, a.w};
            float tt[4] = {t.x, t.y, t.z, t.w};
            #pragma unroll
            for (int k = 0; k < 4; k++) {
                float cdv = __fadd_rn(1.0f, expneg_s(tt[k]));
                if ((int)(__float_as_uint(Dkey_s(aa[k], cdv)) >> 19) <= bcut)
                    push_cand(n, aa[k], tt[k], rb + (hw + k) * NCLS + sg.c);
            }
        } else {
            #pragma unroll
            for (int k = 0; k < 4; k++) {
                int h = hw + k;
                if (h < sg.HW) {
                    float a = lg[h];
                    float tv = ctp[h];
                    float cdv = __fadd_rn(1.0f, expneg_s(tv));
                    if ((int)(__float_as_uint(Dkey_s(a, cdv)) >> 19) <= bcut)
                        push_cand(n, a, tv, rb + h * NCLS + sg.c);
                }
            }
        }
    }
}

__global__ void __launch_bounds__(1024) k_sort(P5 p, float* out) {
    __shared__ union { int hist[8192]; unsigned long long buf[2048]; } u;  // 32KB
    __shared__ int wtot[32], wsuf[32];
    __shared__ int m, bs;
    int n = blockIdx.x, tid = threadIdx.x, nt = blockDim.x;
    int lane = tid & 31, w = tid >> 5;
    int cnt = min(g_cnt[n], CAP);
    for (int i = tid; i < 8192; i += nt) u.hist[i] = 0;
    if (tid == 0) { m = 0; bs = 0; }
    __syncthreads();

    for (int i = tid; i < cnt; i += nt)
        atomicAdd(&u.hist[(int)(g_cand[n][i] >> 51)], 1);
    __syncthreads();

    // hierarchical descending rank-select over 8192 buckets
    int s8 = 0;
    #pragma unroll
    for (int j = 0; j < 8; j++) s8 += u.hist[tid * 8 + j];
    int suf = s8;
    #pragma unroll
    for (int o = 1; o < 32; o <<= 1) {
        int t2 = __shfl_down_sync(0xffffffffu, suf, o);
        if (lane + o < 32) suf += t2;
    }
    if (lane == 0) wtot[w] = suf;
    __syncthreads();
    if (tid < 32) {
        int v = wtot[tid];
        int s = v;
        #pragma unroll
        for (int o = 1; o < 32; o <<= 1) {
            int t2 = __shfl_down_sync(0xffffffffu, s, o);
            if (tid + o < 32) s += t2;
        }
        wsuf[tid] = s - v;
    }
    __syncthreads();
    int above = wsuf[w] + (suf - s8);
    if (above < NREF && above + s8 >= NREF) {
        int cum = above;
        #pragma unroll
        for (int b = 7; b >= 0; b--) {
            cum += u.hist[tid * 8 + b];
            if (cum >= NREF) { bs = tid * 8 + b; break; }
        }
    }
    __syncthreads();
    int bcut2 = bs;
    __syncthreads();                     // hist dead; buf overlay safe

    for (int i = tid; i < cnt; i += nt) {
        unsigned long long kk = g_cand[n][i];
        if ((int)(kk >> 51) >= bcut2) {
            int pos = atomicAdd(&m, 1);
            if (pos < 2048) u.buf[pos] = kk;
        }
    }
    __syncthreads();
    int mm = min(m, 2048);
    int S = (mm <= 512) ? 512 : 2048;    // adaptive sort width (m is ~256+eps)
    for (int i = tid; i < S; i += nt) if (i >= mm) u.buf[i] = 0ULL;
    __syncthreads();

    // bitonic sort descending; keys unique (rank embedded) -> deterministic
    for (int k = 2; k <= S; k <<= 1) {
        for (int j = k >> 1; j > 0; j >>= 1) {
            for (int i = tid; i < S; i += nt) {
                int ixj = i ^ j;
                if (ixj > i) {
                    unsigned long long x = u.buf[i], y = u.buf[ixj];
                    bool desc = ((i & k) == 0);
                    if (desc ? (x < y) : (x > y)) { u.buf[i] = y; u.buf[ixj] = x; }
                }
            }
            __syncthreads();
        }
    }

    if (tid < NREF) {
        unsigned long long kk = u.buf[tid];
        float sc = 0.f, x0 = 0.f, y0 = 0.f, x1 = 0.f, y1 = 0.f;
        int cls = 0, lvl = 0;
        if (kk) {
            float v = __uint_as_float((unsigned)(kk >> 32));
            unsigned rank = 0x7FFFFFFFu - (unsigned)(kk & 0xFFFFFFFFu);
            int l;
            if (rank < 1216000u) l = 0;
            else if (rank < 1520000u) l = 1;
            else if (rank < 1596000u) l = 2;
            else if (rank < 1615760u) l = 3;
            else l = 4;
            int HWl = c_HW[l];
            int r = (int)rank - c_rb[l];
            int loc = r / NCLS;
            cls = r - NCLS * loc;
            lvl = l;
            float strf = c_str[l];
            float px = p.lc[l][2 * loc], py = p.lc[l][2 * loc + 1];
            const float* rg = p.rg[l] + (size_t)n * 4 * HWl;
            float r0 = rg[loc] * strf;
            float r1 = rg[HWl + loc] * strf;
            float r2 = rg[2 * HWl + loc] * strf;
            float r3 = rg[3 * HWl + loc] * strf;
            sc = sqrtf(v);
            x0 = px - r0; y0 = py - r1; x1 = px + r2; y1 = py + r3;
        }
        int o = n * NREF + tid;
        out[o] = sc;
        float* ob = out + NIMG * NREF;
        ob[o * 4 + 0] = x0; ob[o * 4 + 1] = y0;
        ob[o * 4 + 2] = x1; ob[o * 4 + 3] = y1;
        float* oc = out + NIMG * NREF * 5;
        oc[o] = (float)cls;
        float* ol = out + NIMG * NREF * 6;
        ol[o] = (float)lvl;
    }
}

extern "C" void kernel_launch(void* const* d_in, const int* in_sizes, int n_in,
                              void* d_out, int out_size) {
    P5 p;
    for (int l = 0; l < 5; l++) {
        p.lg[l] = (const float*)d_in[4 * l + 0];
        p.rg[l] = (const float*)d_in[4 * l + 1];
        p.ct[l] = (const float*)d_in[4 * l + 2];
        p.lc[l] = (const float*)d_in[4 * l + 3];
    }
    dim3 g(102, NIMG);       // 102*8 = 816 warps >= 810 per image
    k_minred<<<g, 256>>>(p);
    k_cut<<<NIMG, 512>>>();
    dim3 gc(256, NIMG);      // R10-proven compact config
    k_compact<<<gc, 256>>>(p);
    k_sort<<<NIMG, 1024>>>(p, (float*)d_out);
}

// round 14
// speedup vs baseline: 1.1816x; 1.0313x over previous
#include <cuda_runtime.h>
#include <math.h>

#define NIMG 16
#define NCLS 80
#define NREF 256
#define CAP  8192
#define LCAP 8192
#define NSEG 6480       // segments per image (class-aligned 256-chunks)
#define NSEGPAD 6528
#define NW2  810        // minred warps per image (8 classes x 256 hw each)

#define MAGICF 12582912.0f              // 1.5 * 2^23 : round-to-nearest-int magic
#define KC (127 - 0x4B400000)           // exponent rebias for magic-rounded y
#define C1F 0.70710678f                 // quad minimax of 2^f on [-0.5, 0.5]
#define C2F 0.24264069f

typedef unsigned long long u64;

// ---------------- scratch (device globals; no allocs) ----------------
__device__ float g_segD[NIMG * NSEGPAD];            // per-segment min D
__device__ int   g_bcut[NIMG];
__device__ int   g_cnt[NIMG];
__device__ int   g_lcnt[NIMG];
__device__ int   g_seglist[NIMG][LCAP];
__device__ unsigned long long g_cand[NIMG][CAP];

struct P5 { const float* lg[5]; const float* rg[5]; const float* ct[5]; const float* lc[5]; };

__constant__ int c_HW[5]   = {15200, 3800, 950, 247, 70};
__constant__ int c_rb[5]   = {0, 1216000, 1520000, 1596000, 1615760};
__constant__ int c_spc[5]  = {60, 15, 4, 1, 1};
__constant__ int c_segb[5] = {0, 4800, 6000, 6320, 6400};
__constant__ float c_str[5] = {8.f, 16.f, 32.f, 64.f, 128.f};

// ---- packed f32x2 helpers (Blackwell PTX) ----
__device__ __forceinline__ u64 pk2(float lo, float hi) {
    u64 r; asm("mov.b64 %0,{%1,%2};" : "=l"(r) : "f"(lo), "f"(hi)); return r;
}
__device__ __forceinline__ void upk2(u64 v, float& lo, float& hi) {
    asm("mov.b64 {%0,%1},%2;" : "=f"(lo), "=f"(hi) : "l"(v));
}
__device__ __forceinline__ u64 mul2(u64 a, u64 b) {
    u64 r; asm("mul.rn.f32x2 %0,%1,%2;" : "=l"(r) : "l"(a), "l"(b)); return r;
}
__device__ __forceinline__ u64 add2(u64 a, u64 b) {
    u64 r; asm("add.rn.f32x2 %0,%1,%2;" : "=l"(r) : "l"(a), "l"(b)); return r;
}
__device__ __forceinline__ u64 fma2(u64 a, u64 b, u64 c) {
    u64 r; asm("fma.rn.f32x2 %0,%1,%2,%3;" : "=l"(r) : "l"(a), "l"(b), "l"(c)); return r;
}

// Scalar surrogate e^{-x}: magic-round exp2 split + quad minimax. Contraction-proof
// (__fmul_rn/__fadd_rn/fmaf): BITWISE identical to the packed expneg2 below.
__device__ __forceinline__ float expneg_s(float x) {
    float u = __fmul_rn(-1.44269504f, x);
    float y = __fadd_rn(u, MAGICF);
    int iy = __float_as_int(y);
    float yf = __fadd_rn(y, -MAGICF);
    float f = fmaf(yf, -1.0f, u);
    float pm = fmaf(fmaf(C2F, f, C1F), f, 1.0f);
    float sc = __int_as_float((iy + KC) << 23);
    return __fmul_rn(pm, sc);
}

// packed twin of expneg_s (per-lane IEEE rn ops -> identical bits)
__device__ __forceinline__ u64 expneg2(u64 x) {
    const u64 NL2  = pk2(-1.44269504f, -1.44269504f);
    const u64 MG   = pk2(MAGICF, MAGICF);
    const u64 NMG  = pk2(-MAGICF, -MAGICF);
    const u64 NONE = pk2(-1.0f, -1.0f);
    const u64 C2P  = pk2(C2F, C2F);
    const u64 C1P  = pk2(C1F, C1F);
    const u64 ONE  = pk2(1.0f, 1.0f);
    u64 u = mul2(x, NL2);
    u64 y = add2(u, MG);
    float ylo, yhi; upk2(y, ylo, yhi);
    u64 yf = add2(y, NMG);
    u64 f  = fma2(yf, NONE, u);
    u64 pm = fma2(fma2(C2P, f, C1P), f, ONE);
    float slo = __int_as_float((__float_as_int(ylo) + KC) << 23);
    float shi = __int_as_float((__float_as_int(yhi) + KC) << 23);
    return mul2(pm, pk2(slo, shi));
}

// surrogate inverse-score key from logit + precomputed denom cd = 1+e^-c
__device__ __forceinline__ float Dkey_s(float a, float cd) {
    return fmaf(expneg_s(a), cd, cd);             // (1 + e^-a) * cd
}

// Reference-exact sigmoid (libdevice expf == XLA f32 exp), survivors only.
__device__ __forceinline__ float sig_ref(float x) {
    return 1.0f / (1.0f + expf(-x));
}

struct Seg { int l, c, hw0, HW; };
__device__ __forceinline__ Seg seg_decode(int wid) {
    Seg s;
    if (wid < 4800)      { s.l=0; s.c=wid/60;  s.hw0=(wid-s.c*60)<<8;  s.HW=15200; }
    else if (wid < 6000) { int t=wid-4800; s.l=1; s.c=t/15; s.hw0=(t-s.c*15)<<8; s.HW=3800; }
    else if (wid < 6320) { int t=wid-6000; s.l=2; s.c=t>>2; s.hw0=(t&3)<<8; s.HW=950; }
    else if (wid < 6400) { s.l=3; s.c=wid-6320; s.hw0=0; s.HW=247; }
    else                 { s.l=4; s.c=wid-6400; s.hw0=0; s.HW=70; }
    return s;
}

// full pass: each warp handles 8 classes x 256 hw. ct loaded ONCE per window,
// surrogate denom computed inline. Packed f32x2 for levels 0/1; scalar
// (bitwise-identical) for levels 2-4.
__global__ void k_minred(P5 p) {
    int n = blockIdx.y;
    int w2 = blockIdx.x * 8 + (threadIdx.x >> 5);
    int lane = threadIdx.x & 31;
    if (w2 >= NW2) return;
    int l, grp, chunk;
    if (w2 < 600)      { l = 0; grp = w2 / 60;  chunk = w2 - grp * 60; }
    else if (w2 < 750) { int t = w2 - 600; l = 1; grp = t / 15; chunk = t - grp * 15; }
    else if (w2 < 790) { int t = w2 - 750; l = 2; grp = t >> 2; chunk = t & 3; }
    else if (w2 < 800) { l = 3; grp = w2 - 790; chunk = 0; }
    else               { l = 4; grp = w2 - 800; chunk = 0; }
    int HW = c_HW[l];
    int base = (chunk << 8) + lane * 8;
    const float* ctp = p.ct[l] + (size_t)n * HW;
    const float* lg0 = p.lg[l] + ((size_t)n * NCLS + grp * 8) * (size_t)HW;
    float mj[8];
    if (l < 2) {
        bool act = (base + 8 <= HW);
        u64 CD0, CD1, CD2, CD3;
        const u64 ONE = pk2(1.0f, 1.0f);
        if (act) {
            float4 t0 = *(const float4*)(ctp + base);
            float4 t1 = *(const float4*)(ctp + base + 4);
            CD0 = add2(expneg2(pk2(t0.x, t0.y)), ONE);
            CD1 = add2(expneg2(pk2(t0.z, t0.w)), ONE);
            CD2 = add2(expneg2(pk2(t1.x, t1.y)), ONE);
            CD3 = add2(expneg2(pk2(t1.z, t1.w)), ONE);
        }
        #pragma unroll
        for (int j = 0; j < 8; j++) {
            float m = 3.4e38f;
            if (act) {
                const float* lg = lg0 + (size_t)j * HW;
                float4 a0 = *(const float4*)(lg + base);
                float4 a1 = *(const float4*)(lg + base + 4);
                u64 D0 = fma2(expneg2(pk2(a0.x, a0.y)), CD0, CD0);
                u64 D1 = fma2(expneg2(pk2(a0.z, a0.w)), CD1, CD1);
                u64 D2 = fma2(expneg2(pk2(a1.x, a1.y)), CD2, CD2);
                u64 D3 = fma2(expneg2(pk2(a1.z, a1.w)), CD3, CD3);
                float x0, x1, x2, x3, x4, x5, x6, x7;
                upk2(D0, x0, x1); upk2(D1, x2, x3);
                upk2(D2, x4, x5); upk2(D3, x6, x7);
                m = fminf(fminf(fminf(x0, x1), fminf(x2, x3)),
                          fminf(fminf(x4, x5), fminf(x6, x7)));
            }
            mj[j] = m;
        }
    } else {
        float cdv[8];
        #pragma unroll
        for (int k = 0; k < 8; k++) {
            int h = base + k;
            cdv[k] = (h < HW) ? __fadd_rn(1.0f, expneg_s(ctp[h])) : 0.0f;
        }
        #pragma unroll
        for (int j = 0; j < 8; j++) {
            const float* lg = lg0 + (size_t)j * HW;
            float m = 3.4e38f;
            #pragma unroll
            for (int k = 0; k < 8; k++) {
                int h = base + k;
                if (h < HW) m = fminf(m, Dkey_s(lg[h], cdv[k]));
            }
            mj[j] = m;
        }
    }
    #pragma unroll
    for (int j = 0; j < 8; j++) {
        float m = mj[j];
        #pragma unroll
        for (int o = 16; o; o >>= 1)
            m = fminf(m, __shfl_xor_sync(0xffffffffu, m, o));
        mj[j] = m;
    }
    if (lane == 0) {
        int sb = c_segb[l], spc = c_spc[l];
        #pragma unroll
        for (int j = 0; j < 8; j++)
            g_segD[n * NSEGPAD + sb + (grp * 8 + j) * spc + chunk] = mj[j];
    }
}

// ascending rank-select over 4096 buckets of seg-mins, then build seglist.
__global__ void __launch_bounds__(512) k_cut() {
    __shared__ int hist[4096];
    __shared__ int wtot[16], wpre[16];
    __shared__ int bres, lcnt_s;
    int n = blockIdx.x, tid = threadIdx.x, nt = blockDim.x;
    int lane = tid & 31, w = tid >> 5;
    for (int i = tid; i < 4096; i += nt) hist[i] = 0;
    if (tid == 0) { bres = 4095; lcnt_s = 0; g_cnt[n] = 0; }
    __syncthreads();
    for (int i = tid; i < NSEG; i += nt) {
        unsigned b = __float_as_uint(g_segD[n * NSEGPAD + i]) >> 19;
        atomicAdd(&hist[min(b, 4095u)], 1);
    }
    __syncthreads();
    int s8 = 0;
    #pragma unroll
    for (int j = 0; j < 8; j++) s8 += hist[tid * 8 + j];
    int pre = s8;
    #pragma unroll
    for (int o = 1; o < 32; o <<= 1) {
        int t2 = __shfl_up_sync(0xffffffffu, pre, o);
        if (lane >= o) pre += t2;
    }
    if (lane == 31) wtot[w] = pre;
    __syncthreads();
    if (tid < 16) {
        int v = wtot[tid];
        int s = v;
        #pragma unroll
        for (int o = 1; o < 16; o <<= 1) {
            int t2 = __shfl_up_sync(0xffffu, s, o);
            if (tid >= o) s += t2;
        }
        wpre[tid] = s - v;
    }
    __syncthreads();
    int excl = wpre[w] + (pre - s8);
    if (excl < NREF && excl + s8 >= NREF) {
        int cum = excl;
        #pragma unroll
        for (int b = 0; b < 8; b++) {
            cum += hist[tid * 8 + b];
            if (cum >= NREF) { bres = tid * 8 + b; break; }
        }
    }
    __syncthreads();
    int bc = min(bres + 1, 4095);       // +1 bucket: surrogate-vs-exact slop
    if (tid == 0) g_bcut[n] = bc;
    for (int i = tid; i < NSEG; i += nt) {
        unsigned b = __float_as_uint(g_segD[n * NSEGPAD + i]) >> 19;
        if ((int)b <= bc) {
            int pos = atomicAdd(&lcnt_s, 1);
            if (pos < LCAP) g_seglist[n][pos] = i;
        }
    }
    __syncthreads();
    if (tid == 0) g_lcnt[n] = min(lcnt_s, LCAP);
}

__device__ __forceinline__ void push_cand(int n, float a, float ctr_v, int rnk) {
    float sa = sig_ref(a);
    if (sa > 0.05f) {                           // exact reference gate
        float v = sa * sig_ref(ctr_v);
        if (v > 0.0f) {
            unsigned long long kk =
                ((unsigned long long)__float_as_uint(v) << 32) |
                (0x7FFFFFFFu - (unsigned)rnk);
            int pos = atomicAdd(&g_cnt[n], 1);
            if (pos < CAP) g_cand[n][pos] = kk;
        }
    }
}

// flattened one-quad-per-thread (R10 proven body), right-sized grid:
// 16K threads/image for ~19K quads -> minimal prologue waste, single wave.
__global__ void k_compact(P5 p) {
    int n = blockIdx.y;
    int bcut = g_bcut[n];
    int lcnt = g_lcnt[n];
    int total = lcnt << 6;              // 64 quads per 256-elem segment
    int stride = gridDim.x * blockDim.x;
    for (int e = blockIdx.x * blockDim.x + threadIdx.x; e < total; e += stride) {
        int si = g_seglist[n][e >> 6];
        Seg sg = seg_decode(si);
        int hw = sg.hw0 + ((e & 63) << 2);
        const float* lg = p.lg[sg.l] + ((size_t)n * NCLS + sg.c) * sg.HW;
        const float* ctp = p.ct[sg.l] + (size_t)n * sg.HW;
        int rb = c_rb[sg.l];
        if (sg.l < 2 && hw + 4 <= sg.HW) {
            float4 a = *(const float4*)(lg + hw);
            float4 t = *(const float4*)(ctp + hw);
            float aa[4] = {a.x, a.y, a.z, a.w};
            float tt[4] = {t.x, t.y, t.z, t.w};
            #pragma unroll
            for (int k = 0; k < 4; k++) {
                float cdv = __fadd_rn(1.0f, expneg_s(tt[k]));
                if ((int)(__float_as_uint(Dkey_s(aa[k], cdv)) >> 19) <= bcut)
                    push_cand(n, aa[k], tt[k], rb + (hw + k) * NCLS + sg.c);
            }
        } else {
            #pragma unroll
            for (int k = 0; k < 4; k++) {
                int h = hw + k;
                if (h < sg.HW) {
                    float a = lg[h];
                    float tv = ctp[h];
                    float cdv = __fadd_rn(1.0f, expneg_s(tv));
                    if ((int)(__float_as_uint(Dkey_s(a, cdv)) >> 19) <= bcut)
                        push_cand(n, a, tv, rb + h * NCLS + sg.c);
                }
            }
        }
    }
}

// top-256: bucket cut -> counting-rank direct scatter (NO bitonic, no barriers
// in the ranking phase). Keys unique (rank embedded) -> exact permutation.
__global__ void __launch_bounds__(1024) k_sort(P5 p, float* out) {
    __shared__ union { int hist[8192]; unsigned long long buf[2048]; } u;  // 32KB
    __shared__ int wtot[32], wsuf[32];
    __shared__ int m, bs;
    int n = blockIdx.x, tid = threadIdx.x, nt = blockDim.x;
    int lane = tid & 31, w = tid >> 5;
    int cnt = min(g_cnt[n], CAP);
    for (int i = tid; i < 8192; i += nt) u.hist[i] = 0;
    if (tid == 0) { m = 0; bs = 0; }
    __syncthreads();

    for (int i = tid; i < cnt; i += nt)
        atomicAdd(&u.hist[(int)(g_cand[n][i] >> 51)], 1);
    __syncthreads();

    // hierarchical descending rank-select over 8192 buckets
    int s8 = 0;
    #pragma unroll
    for (int j = 0; j < 8; j++) s8 += u.hist[tid * 8 + j];
    int suf = s8;
    #pragma unroll
    for (int o = 1; o < 32; o <<= 1) {
        int t2 = __shfl_down_sync(0xffffffffu, suf, o);
        if (lane + o < 32) suf += t2;
    }
    if (lane == 0) wtot[w] = suf;
    __syncthreads();
    if (tid < 32) {
        int v = wtot[tid];
        int s = v;
        #pragma unroll
        for (int o = 1; o < 32; o <<= 1) {
            int t2 = __shfl_down_sync(0xffffffffu, s, o);
            if (tid + o < 32) s += t2;
        }
        wsuf[tid] = s - v;
    }
    __syncthreads();
    int above = wsuf[w] + (suf - s8);
    if (above < NREF && above + s8 >= NREF) {
        int cum = above;
        #pragma unroll
        for (int b = 7; b >= 0; b--) {
            cum += u.hist[tid * 8 + b];
            if (cum >= NREF) { bs = tid * 8 + b; break; }
        }
    }
    __syncthreads();
    int bcut2 = bs;
    __syncthreads();                     // hist dead; buf overlay safe

    // filter survivors into smem
    for (int i = tid; i < cnt; i += nt) {
        unsigned long long kk = g_cand[n][i];
        if ((int)(kk >> 51) >= bcut2) {
            int pos = atomicAdd(&m, 1);
            if (pos < 2048) u.buf[pos] = kk;
        }
    }
    __syncthreads();
    int mm = min(m, 2048);

    // zero-fill output slots [mm, NREF) (disjoint from scatter targets < mm)
    if (tid >= mm && tid < NREF) {
        int o = n * NREF + tid;
        out[o] = 0.f;
        float* ob = out + NIMG * NREF;
        ob[o * 4 + 0] = 0.f; ob[o * 4 + 1] = 0.f;
        ob[o * 4 + 2] = 0.f; ob[o * 4 + 3] = 0.f;
        out[NIMG * NREF * 5 + o] = 0.f;
        out[NIMG * NREF * 6 + o] = 0.f;
    }

    // counting-rank: slot_i = #{j : key_j > key_i}; scatter if slot < NREF
    for (int i = tid; i < mm; i += nt) {
        unsigned long long key = u.buf[i];
        int slot = 0;
        for (int j = 0; j < mm; j++)
            slot += (u.buf[j] > key);
        if (slot < NREF) {
            float v = __uint_as_float((unsigned)(key >> 32));
            unsigned rank = 0x7FFFFFFFu - (unsigned)(key & 0xFFFFFFFFu);
            int l;
            if (rank < 1216000u) l = 0;
            else if (rank < 1520000u) l = 1;
            else if (rank < 1596000u) l = 2;
            else if (rank < 1615760u) l = 3;
            else l = 4;
            int HWl = c_HW[l];
            int r = (int)rank - c_rb[l];
            int loc = r / NCLS;
            int cls = r - NCLS * loc;
            float strf = c_str[l];
            float px = p.lc[l][2 * loc], py = p.lc[l][2 * loc + 1];
            const float* rg = p.rg[l] + (size_t)n * 4 * HWl;
            float r0 = rg[loc] * strf;
            float r1 = rg[HWl + loc] * strf;
            float r2 = rg[2 * HWl + loc] * strf;
            float r3 = rg[3 * HWl + loc] * strf;
            int o = n * NREF + slot;
            out[o] = sqrtf(v);
            float* ob = out + NIMG * NREF;
            ob[o * 4 + 0] = px - r0; ob[o * 4 + 1] = py - r1;
            ob[o * 4 + 2] = px + r2; ob[o * 4 + 3] = py + r3;
            out[NIMG * NREF * 5 + o] = (float)cls;
            out[NIMG * NREF * 6 + o] = (float)l;
        }
    }
}

extern "C" void kernel_launch(void* const* d_in, const int* in_sizes, int n_in,
                              void* d_out, int out_size) {
    P5 p;
    for (int l = 0; l < 5; l++) {
        p.lg[l] = (const float*)d_in[4 * l + 0];
        p.rg[l] = (const float*)d_in[4 * l + 1];
        p.ct[l] = (const float*)d_in[4 * l + 2];
        p.lc[l] = (const float*)d_in[4 * l + 3];
    }
    dim3 g(102, NIMG);       // 102*8 = 816 warps >= 810 per image
    k_minred<<<g, 256>>>(p);
    k_cut<<<NIMG, 512>>>();
    dim3 gc(64, NIMG);       // 16K threads/image, ~1.2 quads per thread
    k_compact<<<gc, 256>>>(p);
    k_sort<<<NIMG, 1024>>>(p, (float*)d_out);
}